// round 13
// baseline (speedup 1.0000x reference)
#include <cuda_runtime.h>
#include <cstdint>

// ---------------------------------------------------------------------------
// Fused top-k triple, single kernel:
//   x: [32,2048,1024] f32 -> top-4 desc per row
//   y: [8,32,2048,64] f32 -> min over dim2 (2048)
//   z: [32,4096,512]  f32 -> top-3 desc values + indices (stable, low idx wins)
// Output f32 layout: x_top[262144] | y_min[16384] | z_top[393216] | z_idx[393216]
//
// R12 failed: arithmetic comparators (fma-pipe) NaN'd on -inf sentinels
// (inf - inf). Fix: seed x's top-4 registers from the first float4 via a
// 5-comparator descending sort — all operands finite (randn), so the
// (a+b)/2 +- |a-b|/2 identity is safe. Theory unchanged: move x's comparator
// network off the saturated alu pipe onto the idle fma pipe.
// ---------------------------------------------------------------------------

#define INFF  (__int_as_float(0x7f800000))
#define NINFF (__int_as_float(0xff800000))

__device__ __forceinline__ float4 ldcs4(const float4* p) {
    return __ldcs(p);
}

// Order-preserving float<->uint mapping (no NaNs in randn inputs).
__device__ __forceinline__ unsigned f2mono(float f) {
    unsigned b = __float_as_uint(f);
    return b ^ ((unsigned)(((int)b) >> 31) | 0x80000000u);
}
__device__ __forceinline__ float mono2f(unsigned u) {
    unsigned mask = ((unsigned)((~(int)u) >> 31)) | 0x80000000u;
    return __uint_as_float(u ^ mask);
}

// fma-pipe compare-swap: a <- ~max(a,b), b <- ~min(a,b); within ~1 ulp.
// FINITE OPERANDS ONLY (inf => NaN). FADD + FADD + FMUL-imm + 2x FFMA-imm.
__device__ __forceinline__ void fpswap(float& a, float& b) {
    float s = a + b;
    float d = fabsf(a - b);
    float h = 0.5f * s;
    a = fmaf( 0.5f, d, h);
    b = fmaf(-0.5f, d, h);
}
__device__ __forceinline__ float fpmax(float a, float b) {
    float s = a + b;
    float d = fabsf(a - b);
    return fmaf(0.5f, d, 0.5f * s);
}

// x top-4 insert, entirely on fma pipe.
#define XINS(w_) do { float _t = (w_);  \
    fpswap(v0, _t);                     \
    fpswap(v1, _t);                     \
    fpswap(v2, _t);                     \
    v3 = fpmax(v3, _t); } while (0)

// Branchless sorted-descending top-3 insert with index (exact, alu pipe).
// Strict > with ascending-index processing == jax.lax.top_k stability.
#define ZINS(w_, wi_) do { float _w = (w_); int _wi = (wi_);              \
    bool _g0 = _w > v0, _g1 = _w > v1, _g2 = _w > v2;                     \
    float _nv1 = _g1 ? (_g0 ? v0 : _w) : v1;                              \
    int   _ni1 = _g1 ? (_g0 ? i0 : _wi) : i1;                             \
    float _nv2 = _g2 ? (_g1 ? v1 : _w) : v2;                              \
    int   _ni2 = _g2 ? (_g1 ? i1 : _wi) : i2;                             \
    v0 = _g0 ? _w : v0;  i0 = _g0 ? _wi : i0;                             \
    v1 = _nv1; i1 = _ni1; v2 = _nv2; i2 = _ni2; } while (0)

// ---------------------------------------------------------------------------
// Mega kernel: block dispatch (y first: 512KB long-poles start in wave 1)
//   [0,      256) -> y full min     (block per pair, 2048x64 slab)
//   [256,  16640) -> z top-3        (warp/row, 131072 rows of 512)
//   [16640, 24832)-> x top-4        (warp/row, 65536 rows of 1024)
// ---------------------------------------------------------------------------
__global__ __launch_bounds__(256) void mega(const float* __restrict__ x,
                                            const float* __restrict__ y,
                                            const float* __restrict__ z,
                                            float* __restrict__ x_out,
                                            float* __restrict__ y_out,
                                            float* __restrict__ z_val,
                                            float* __restrict__ z_idx) {
    const int bid = blockIdx.x;
    const int tid = threadIdx.x;
    __shared__ float4 s[256];

    if (bid < 256) {
        // ---------------- y: full min over dim2 (one block per pair) -------
        const int pair = bid;              // b0*32 + b1
        const int h4   = tid & 15;         // float4 column group
        const int tsub = tid >> 4;         // 0..15 (t stripe)

        const float4* p = reinterpret_cast<const float4*>(y)
                        + (size_t)pair * 2048 * 16;

        float4 m; m.x = INFF; m.y = INFF; m.z = INFF; m.w = INFF;

        #pragma unroll 8
        for (int t = tsub; t < 2048; t += 16) {
            float4 q = ldcs4(p + t * 16 + h4);
            m.x = fminf(m.x, q.x); m.y = fminf(m.y, q.y);
            m.z = fminf(m.z, q.z); m.w = fminf(m.w, q.w);
        }

        s[tid] = m;
        __syncthreads();

        #pragma unroll
        for (int str = 128; str >= 16; str >>= 1) {
            if (tid < str) {
                float4 a = s[tid], b = s[tid + str];
                a.x = fminf(a.x, b.x); a.y = fminf(a.y, b.y);
                a.z = fminf(a.z, b.z); a.w = fminf(a.w, b.w);
                s[tid] = a;
            }
            __syncthreads();
        }

        if (tid < 16) {
            reinterpret_cast<float4*>(y_out)[pair * 16 + tid] = s[tid];
        }

    } else if (bid < 16640) {
        // ---------------- z: top-3 values + indices (exact) ----------------
        const int row  = (bid - 256) * 8 + (tid >> 5);
        const int lane = tid & 31;
        const float4* p = reinterpret_cast<const float4*>(z) + (size_t)row * 128;

        float v0 = NINFF, v1 = NINFF, v2 = NINFF;
        int   i0 = 0, i1 = 0, i2 = 0;
        const int il = lane * 4;

        #pragma unroll
        for (int k = 0; k < 4; k++) {
            float4 q = ldcs4(p + lane + k * 32);
            const int base = il + k * 128;      // element idx = 4*(lane+32k)+c
            ZINS(q.x, base + 0);
            ZINS(q.y, base + 1);
            ZINS(q.z, base + 2);
            ZINS(q.w, base + 3);
        }

        // Warp merge via REDUX rounds on monotone keys.
        unsigned m0 = f2mono(v0), m1 = f2mono(v1), m2 = f2mono(v2);
        unsigned bv[3], bi[3];
        #pragma unroll
        for (int r = 0; r < 3; r++) {
            unsigned best = __reduce_max_sync(0xffffffffu, m0);
            unsigned cand = (m0 == best) ? (unsigned)i0 : 0xffffffffu;
            unsigned bidx = __reduce_min_sync(0xffffffffu, cand);
            bool pop = (m0 == best) && ((unsigned)i0 == bidx);
            m0 = pop ? m1 : m0;  i0 = pop ? i1 : i0;
            m1 = pop ? m2 : m1;  i1 = pop ? i2 : i1;
            m2 = pop ? 0u : m2;
            bv[r] = best; bi[r] = bidx;
        }

        if (lane == 0) {
            const size_t o = (size_t)row * 3;
            z_val[o + 0] = mono2f(bv[0]);
            z_val[o + 1] = mono2f(bv[1]);
            z_val[o + 2] = mono2f(bv[2]);
            z_idx[o + 0] = (float)bi[0];
            z_idx[o + 1] = (float)bi[1];
            z_idx[o + 2] = (float)bi[2];
        }

    } else {
        // ---------------- x: top-4 values (fma-pipe comparators) -----------
        const int row  = (bid - 16640) * 8 + (tid >> 5);
        const int lane = tid & 31;
        const float4* p = reinterpret_cast<const float4*>(x) + (size_t)row * 256;

        // Seed from the first float4 (finite randn values -> fpswap is safe),
        // sorted descending with a 5-comparator network.
        float4 q0 = ldcs4(p + lane);
        float v0 = q0.x, v1 = q0.y, v2 = q0.z, v3 = q0.w;
        fpswap(v0, v1); fpswap(v2, v3);
        fpswap(v0, v2); fpswap(v1, v3);
        fpswap(v1, v2);

        #pragma unroll
        for (int k = 1; k < 8; k++) {
            float4 q = ldcs4(p + lane + k * 32);
            XINS(q.x); XINS(q.y); XINS(q.z); XINS(q.w);
        }

        unsigned m0 = f2mono(v0), m1 = f2mono(v1), m2 = f2mono(v2), m3 = f2mono(v3);
        unsigned bv[4];
        #pragma unroll
        for (int r = 0; r < 4; r++) {
            unsigned best = __reduce_max_sync(0xffffffffu, m0);
            unsigned mask = __ballot_sync(0xffffffffu, m0 == best);
            bool pop = (lane == (__ffs(mask) - 1));   // exactly one lane pops
            m0 = pop ? m1 : m0;
            m1 = pop ? m2 : m1;
            m2 = pop ? m3 : m2;
            m3 = pop ? 0u : m3;
            bv[r] = best;
        }

        if (lane == 0) {
            float4 r;
            r.x = mono2f(bv[0]); r.y = mono2f(bv[1]);
            r.z = mono2f(bv[2]); r.w = mono2f(bv[3]);
            reinterpret_cast<float4*>(x_out)[row] = r;
        }
    }
}

// ---------------------------------------------------------------------------
extern "C" void kernel_launch(void* const* d_in, const int* in_sizes, int n_in,
                              void* d_out, int out_size) {
    const float* x = (const float*)d_in[0];   // 32*2048*1024
    const float* y = (const float*)d_in[1];   // 8*32*2048*64
    const float* z = (const float*)d_in[2];   // 32*4096*512

    float* out   = (float*)d_out;
    float* x_out = out;
    float* y_out = out + 262144;
    float* z_val = out + 278528;
    float* z_idx = out + 671744;

    mega<<<24832, 256>>>(x, y, z, x_out, y_out, z_val, z_idx);
}

// round 14
// speedup vs baseline: 1.5360x; 1.5360x over previous
#include <cuda_runtime.h>
#include <cstdint>

// ---------------------------------------------------------------------------
// Fused top-k triple, single kernel:
//   x: [32,2048,1024] f32 -> top-4 desc per row
//   y: [8,32,2048,64] f32 -> min over dim2 (2048)
//   z: [32,4096,512]  f32 -> top-3 desc values + indices (stable, low idx wins)
// Output f32 layout: x_top[262144] | y_min[16384] | z_top[393216] | z_idx[393216]
//
// R13 post-mortem: fma-comparator x was 18 ops/elem vs 7 FMNMX — reverted.
// R14: z phase alone is alu-bound (13 alu/elem needs 1.44x alu cap at full
// HBM rate); x phase is memory-bound (7/elem). R11 ran them as separate grid
// phases -> blended 83% DRAM. This round interleaves the dispatch [z,z,x]
// per 3-block group so every wave carries the balanced mix (avg 8.2 ops/elem
// = 91% alu cap at 100% DRAM). y long-poles stay at bids 0..255 (must be
// wave-1 resident; each streams 512KB across the whole kernel).
// ---------------------------------------------------------------------------

#define INFF  (__int_as_float(0x7f800000))
#define NINFF (__int_as_float(0xff800000))

__device__ __forceinline__ float4 ldcs4(const float4* p) {
    return __ldcs(p);
}

// Order-preserving float<->uint mapping (no NaNs in randn inputs).
__device__ __forceinline__ unsigned f2mono(float f) {
    unsigned b = __float_as_uint(f);
    return b ^ ((unsigned)(((int)b) >> 31) | 0x80000000u);
}
__device__ __forceinline__ float mono2f(unsigned u) {
    unsigned mask = ((unsigned)((~(int)u) >> 31)) | 0x80000000u;
    return __uint_as_float(u ^ mask);
}

// Branchless sorted-descending top-4 insert (values only): 7 FMNMX, exact.
#define XINS(w_) do { float _w = (w_);                     \
    float _a = fmaxf(_w, v0); float _b = fminf(_w, v0);    \
    float _c = fmaxf(_b, v1); float _d = fminf(_b, v1);    \
    float _e = fmaxf(_d, v2); float _f = fminf(_d, v2);    \
    v0 = _a; v1 = _c; v2 = _e; v3 = fmaxf(_f, v3); } while (0)

// Branchless sorted-descending top-3 insert with index (exact).
// Strict > with ascending-index processing == jax.lax.top_k stability.
#define ZINS(w_, wi_) do { float _w = (w_); int _wi = (wi_);              \
    bool _g0 = _w > v0, _g1 = _w > v1, _g2 = _w > v2;                     \
    float _nv1 = _g1 ? (_g0 ? v0 : _w) : v1;                              \
    int   _ni1 = _g1 ? (_g0 ? i0 : _wi) : i1;                             \
    float _nv2 = _g2 ? (_g1 ? v1 : _w) : v2;                              \
    int   _ni2 = _g2 ? (_g1 ? i1 : _wi) : i2;                             \
    v0 = _g0 ? _w : v0;  i0 = _g0 ? _wi : i0;                             \
    v1 = _nv1; i1 = _ni1; v2 = _nv2; i2 = _ni2; } while (0)

// ---------------------------------------------------------------------------
// Mega kernel. Dispatch:
//   bids [0,256): y (block per pair, wave-1 long poles)
//   bids [256,24832): t = bid-256; t%3<2 -> z block (t/3)*2+(t%3)
//                                  t%3==2 -> x block (t/3)
// Every post-wave-1 wave mixes ~2/3 z (alu-heavy) + 1/3 x (alu-light).
// ---------------------------------------------------------------------------
__global__ __launch_bounds__(256) void mega(const float* __restrict__ x,
                                            const float* __restrict__ y,
                                            const float* __restrict__ z,
                                            float* __restrict__ x_out,
                                            float* __restrict__ y_out,
                                            float* __restrict__ z_val,
                                            float* __restrict__ z_idx) {
    const int bid = blockIdx.x;
    const int tid = threadIdx.x;
    __shared__ float4 s[256];

    if (bid < 256) {
        // ---------------- y: full min over dim2 (one block per pair) -------
        const int pair = bid;              // b0*32 + b1
        const int h4   = tid & 15;         // float4 column group
        const int tsub = tid >> 4;         // 0..15 (t stripe)

        const float4* p = reinterpret_cast<const float4*>(y)
                        + (size_t)pair * 2048 * 16;

        float4 m; m.x = INFF; m.y = INFF; m.z = INFF; m.w = INFF;

        #pragma unroll 8
        for (int t = tsub; t < 2048; t += 16) {
            float4 q = ldcs4(p + t * 16 + h4);
            m.x = fminf(m.x, q.x); m.y = fminf(m.y, q.y);
            m.z = fminf(m.z, q.z); m.w = fminf(m.w, q.w);
        }

        s[tid] = m;
        __syncthreads();

        #pragma unroll
        for (int str = 128; str >= 16; str >>= 1) {
            if (tid < str) {
                float4 a = s[tid], b = s[tid + str];
                a.x = fminf(a.x, b.x); a.y = fminf(a.y, b.y);
                a.z = fminf(a.z, b.z); a.w = fminf(a.w, b.w);
                s[tid] = a;
            }
            __syncthreads();
        }

        if (tid < 16) {
            reinterpret_cast<float4*>(y_out)[pair * 16 + tid] = s[tid];
        }
        return;
    }

    const int t   = bid - 256;
    const int grp = t / 3;
    const int rem = t - grp * 3;

    if (rem < 2) {
        // ---------------- z: top-3 values + indices (exact) ----------------
        const int zb   = grp * 2 + rem;              // 0..16383
        const int row  = zb * 8 + (tid >> 5);
        const int lane = tid & 31;
        const float4* p = reinterpret_cast<const float4*>(z) + (size_t)row * 128;

        float v0 = NINFF, v1 = NINFF, v2 = NINFF;
        int   i0 = 0, i1 = 0, i2 = 0;
        const int il = lane * 4;

        #pragma unroll
        for (int k = 0; k < 4; k++) {
            float4 q = ldcs4(p + lane + k * 32);
            const int base = il + k * 128;      // element idx = 4*(lane+32k)+c
            ZINS(q.x, base + 0);
            ZINS(q.y, base + 1);
            ZINS(q.z, base + 2);
            ZINS(q.w, base + 3);
        }

        // Warp merge via REDUX rounds on monotone keys.
        unsigned m0 = f2mono(v0), m1 = f2mono(v1), m2 = f2mono(v2);
        unsigned bv[3], bi[3];
        #pragma unroll
        for (int r = 0; r < 3; r++) {
            unsigned best = __reduce_max_sync(0xffffffffu, m0);
            unsigned cand = (m0 == best) ? (unsigned)i0 : 0xffffffffu;
            unsigned bidx = __reduce_min_sync(0xffffffffu, cand);
            bool pop = (m0 == best) && ((unsigned)i0 == bidx);
            m0 = pop ? m1 : m0;  i0 = pop ? i1 : i0;
            m1 = pop ? m2 : m1;  i1 = pop ? i2 : i1;
            m2 = pop ? 0u : m2;
            bv[r] = best; bi[r] = bidx;
        }

        if (lane == 0) {
            const size_t o = (size_t)row * 3;
            z_val[o + 0] = mono2f(bv[0]);
            z_val[o + 1] = mono2f(bv[1]);
            z_val[o + 2] = mono2f(bv[2]);
            z_idx[o + 0] = (float)bi[0];
            z_idx[o + 1] = (float)bi[1];
            z_idx[o + 2] = (float)bi[2];
        }

    } else {
        // ---------------- x: top-4 values (exact FMNMX network) ------------
        const int xb   = grp;                        // 0..8191
        const int row  = xb * 8 + (tid >> 5);
        const int lane = tid & 31;
        const float4* p = reinterpret_cast<const float4*>(x) + (size_t)row * 256;

        float v0 = NINFF, v1 = NINFF, v2 = NINFF, v3 = NINFF;

        #pragma unroll
        for (int k = 0; k < 8; k++) {
            float4 q = ldcs4(p + lane + k * 32);
            XINS(q.x); XINS(q.y); XINS(q.z); XINS(q.w);
        }

        unsigned m0 = f2mono(v0), m1 = f2mono(v1), m2 = f2mono(v2), m3 = f2mono(v3);
        unsigned bv[4];
        #pragma unroll
        for (int r = 0; r < 4; r++) {
            unsigned best = __reduce_max_sync(0xffffffffu, m0);
            unsigned mask = __ballot_sync(0xffffffffu, m0 == best);
            bool pop = (lane == (__ffs(mask) - 1));   // exactly one lane pops
            m0 = pop ? m1 : m0;
            m1 = pop ? m2 : m1;
            m2 = pop ? m3 : m2;
            m3 = pop ? 0u : m3;
            bv[r] = best;
        }

        if (lane == 0) {
            float4 r;
            r.x = mono2f(bv[0]); r.y = mono2f(bv[1]);
            r.z = mono2f(bv[2]); r.w = mono2f(bv[3]);
            reinterpret_cast<float4*>(x_out)[row] = r;
        }
    }
}

// ---------------------------------------------------------------------------
extern "C" void kernel_launch(void* const* d_in, const int* in_sizes, int n_in,
                              void* d_out, int out_size) {
    const float* x = (const float*)d_in[0];   // 32*2048*1024
    const float* y = (const float*)d_in[1];   // 8*32*2048*64
    const float* z = (const float*)d_in[2];   // 32*4096*512

    float* out   = (float*)d_out;
    float* x_out = out;
    float* y_out = out + 262144;
    float* z_val = out + 278528;
    float* z_idx = out + 671744;

    mega<<<24832, 256>>>(x, y, z, x_out, y_out, z_val, z_idx);
}

// round 16
// speedup vs baseline: 1.5403x; 1.0028x over previous
#include <cuda_runtime.h>
#include <cstdint>

// ---------------------------------------------------------------------------
// Fused top-k triple, single kernel:
//   x: [32,2048,1024] f32 -> top-4 desc per row
//   y: [8,32,2048,64] f32 -> min over dim2 (2048)
//   z: [32,4096,512]  f32 -> top-3 desc values + indices (stable, low idx wins)
// Output f32 layout: x_top[262144] | y_min[16384] | z_top[393216] | z_idx[393216]
//
// R14 post-mortem: interleaving didn't move DRAM% — we sit at 6.6 TB/s which
// is ~96% of the LTS full-chip cap (~6300 B/cyc), i.e. near the REAL ceiling.
// This round targets the last few %: regs=32 prevented load front-batching
// (MLP ~1-2/warp). Explicitly batch 4 float4 loads before consuming (z: all
// 16 elems; x: 2 halves of 4), launch_bounds(256,7) to allow ~36 regs.
// ---------------------------------------------------------------------------

#define INFF  (__int_as_float(0x7f800000))
#define NINFF (__int_as_float(0xff800000))

__device__ __forceinline__ float4 ldcs4(const float4* p) {
    return __ldcs(p);
}

// Order-preserving float<->uint mapping (no NaNs in randn inputs).
__device__ __forceinline__ unsigned f2mono(float f) {
    unsigned b = __float_as_uint(f);
    return b ^ ((unsigned)(((int)b) >> 31) | 0x80000000u);
}
__device__ __forceinline__ float mono2f(unsigned u) {
    unsigned mask = ((unsigned)((~(int)u) >> 31)) | 0x80000000u;
    return __uint_as_float(u ^ mask);
}

// Branchless sorted-descending top-4 insert (values only): 7 FMNMX, exact.
#define XINS(w_) do { float _w = (w_);                     \
    float _a = fmaxf(_w, v0); float _b = fminf(_w, v0);    \
    float _c = fmaxf(_b, v1); float _d = fminf(_b, v1);    \
    float _e = fmaxf(_d, v2); float _f = fminf(_d, v2);    \
    v0 = _a; v1 = _c; v2 = _e; v3 = fmaxf(_f, v3); } while (0)

// Branchless sorted-descending top-3 insert with index (exact).
// Strict > with ascending-index processing == jax.lax.top_k stability.
#define ZINS(w_, wi_) do { float _w = (w_); int _wi = (wi_);              \
    bool _g0 = _w > v0, _g1 = _w > v1, _g2 = _w > v2;                     \
    float _nv1 = _g1 ? (_g0 ? v0 : _w) : v1;                              \
    int   _ni1 = _g1 ? (_g0 ? i0 : _wi) : i1;                             \
    float _nv2 = _g2 ? (_g1 ? v1 : _w) : v2;                              \
    int   _ni2 = _g2 ? (_g1 ? i1 : _wi) : i2;                             \
    v0 = _g0 ? _w : v0;  i0 = _g0 ? _wi : i0;                             \
    v1 = _nv1; i1 = _ni1; v2 = _nv2; i2 = _ni2; } while (0)

// ---------------------------------------------------------------------------
// Mega kernel. Dispatch:
//   bids [0,256): y (block per pair, wave-1 long poles)
//   bids [256,24832): t = bid-256; t%3<2 -> z block (t/3)*2+(t%3)
//                                  t%3==2 -> x block (t/3)
// ---------------------------------------------------------------------------
__global__ __launch_bounds__(256, 7) void mega(const float* __restrict__ x,
                                               const float* __restrict__ y,
                                               const float* __restrict__ z,
                                               float* __restrict__ x_out,
                                               float* __restrict__ y_out,
                                               float* __restrict__ z_val,
                                               float* __restrict__ z_idx) {
    const int bid = blockIdx.x;
    const int tid = threadIdx.x;
    __shared__ float4 s[256];

    if (bid < 256) {
        // ---------------- y: full min over dim2 (one block per pair) -------
        const int pair = bid;              // b0*32 + b1
        const int h4   = tid & 15;         // float4 column group
        const int tsub = tid >> 4;         // 0..15 (t stripe)

        const float4* p = reinterpret_cast<const float4*>(y)
                        + (size_t)pair * 2048 * 16;

        float4 m; m.x = INFF; m.y = INFF; m.z = INFF; m.w = INFF;

        // Batch 4 loads per iteration for MLP.
        #pragma unroll 2
        for (int t = tsub; t < 2048; t += 64) {
            float4 qa = ldcs4(p + (t     ) * 16 + h4);
            float4 qb = ldcs4(p + (t + 16) * 16 + h4);
            float4 qc = ldcs4(p + (t + 32) * 16 + h4);
            float4 qd = ldcs4(p + (t + 48) * 16 + h4);
            m.x = fminf(fminf(fminf(m.x, qa.x), fminf(qb.x, qc.x)), qd.x);
            m.y = fminf(fminf(fminf(m.y, qa.y), fminf(qb.y, qc.y)), qd.y);
            m.z = fminf(fminf(fminf(m.z, qa.z), fminf(qb.z, qc.z)), qd.z);
            m.w = fminf(fminf(fminf(m.w, qa.w), fminf(qb.w, qc.w)), qd.w);
        }

        s[tid] = m;
        __syncthreads();

        #pragma unroll
        for (int str = 128; str >= 16; str >>= 1) {
            if (tid < str) {
                float4 a = s[tid], b = s[tid + str];
                a.x = fminf(a.x, b.x); a.y = fminf(a.y, b.y);
                a.z = fminf(a.z, b.z); a.w = fminf(a.w, b.w);
                s[tid] = a;
            }
            __syncthreads();
        }

        if (tid < 16) {
            reinterpret_cast<float4*>(y_out)[pair * 16 + tid] = s[tid];
        }
        return;
    }

    const int t   = bid - 256;
    const int grp = t / 3;
    const int rem = t - grp * 3;

    if (rem < 2) {
        // ---------------- z: top-3 values + indices (exact) ----------------
        const int zb   = grp * 2 + rem;              // 0..16383
        const int row  = zb * 8 + (tid >> 5);
        const int lane = tid & 31;
        const float4* p = reinterpret_cast<const float4*>(z) + (size_t)row * 128;

        // Front-batch all 4 loads (lane's entire 16 elements): MLP_p1 = 4.
        float4 qa = ldcs4(p + lane);
        float4 qb = ldcs4(p + lane + 32);
        float4 qc = ldcs4(p + lane + 64);
        float4 qd = ldcs4(p + lane + 96);

        float v0 = NINFF, v1 = NINFF, v2 = NINFF;
        int   i0 = 0, i1 = 0, i2 = 0;
        const int il = lane * 4;

        ZINS(qa.x, il + 0);   ZINS(qa.y, il + 1);
        ZINS(qa.z, il + 2);   ZINS(qa.w, il + 3);
        ZINS(qb.x, il + 128); ZINS(qb.y, il + 129);
        ZINS(qb.z, il + 130); ZINS(qb.w, il + 131);
        ZINS(qc.x, il + 256); ZINS(qc.y, il + 257);
        ZINS(qc.z, il + 258); ZINS(qc.w, il + 259);
        ZINS(qd.x, il + 384); ZINS(qd.y, il + 385);
        ZINS(qd.z, il + 386); ZINS(qd.w, il + 387);

        // Warp merge via REDUX rounds on monotone keys.
        unsigned m0 = f2mono(v0), m1 = f2mono(v1), m2 = f2mono(v2);
        unsigned bv[3], bi[3];
        #pragma unroll
        for (int r = 0; r < 3; r++) {
            unsigned best = __reduce_max_sync(0xffffffffu, m0);
            unsigned cand = (m0 == best) ? (unsigned)i0 : 0xffffffffu;
            unsigned bidx = __reduce_min_sync(0xffffffffu, cand);
            bool pop = (m0 == best) && ((unsigned)i0 == bidx);
            m0 = pop ? m1 : m0;  i0 = pop ? i1 : i0;
            m1 = pop ? m2 : m1;  i1 = pop ? i2 : i1;
            m2 = pop ? 0u : m2;
            bv[r] = best; bi[r] = bidx;
        }

        if (lane == 0) {
            const size_t o = (size_t)row * 3;
            z_val[o + 0] = mono2f(bv[0]);
            z_val[o + 1] = mono2f(bv[1]);
            z_val[o + 2] = mono2f(bv[2]);
            z_idx[o + 0] = (float)bi[0];
            z_idx[o + 1] = (float)bi[1];
            z_idx[o + 2] = (float)bi[2];
        }

    } else {
        // ---------------- x: top-4 values (exact FMNMX network) ------------
        const int xb   = grp;                        // 0..8191
        const int row  = xb * 8 + (tid >> 5);
        const int lane = tid & 31;
        const float4* p = reinterpret_cast<const float4*>(x) + (size_t)row * 256;

        float v0 = NINFF, v1 = NINFF, v2 = NINFF, v3 = NINFF;

        // Two front-batched groups of 4 loads: MLP_p1 = 4.
        #pragma unroll
        for (int h = 0; h < 2; h++) {
            const float4* q = p + lane + h * 128;
            float4 qa = ldcs4(q);
            float4 qb = ldcs4(q + 32);
            float4 qc = ldcs4(q + 64);
            float4 qd = ldcs4(q + 96);
            XINS(qa.x); XINS(qa.y); XINS(qa.z); XINS(qa.w);
            XINS(qb.x); XINS(qb.y); XINS(qb.z); XINS(qb.w);
            XINS(qc.x); XINS(qc.y); XINS(qc.z); XINS(qc.w);
            XINS(qd.x); XINS(qd.y); XINS(qd.z); XINS(qd.w);
        }

        unsigned m0 = f2mono(v0), m1 = f2mono(v1), m2 = f2mono(v2), m3 = f2mono(v3);
        unsigned bv[4];
        #pragma unroll
        for (int r = 0; r < 4; r++) {
            unsigned best = __reduce_max_sync(0xffffffffu, m0);
            unsigned mask = __ballot_sync(0xffffffffu, m0 == best);
            bool pop = (lane == (__ffs(mask) - 1));   // exactly one lane pops
            m0 = pop ? m1 : m0;
            m1 = pop ? m2 : m1;
            m2 = pop ? m3 : m2;
            m3 = pop ? 0u : m3;
            bv[r] = best;
        }

        if (lane == 0) {
            float4 r;
            r.x = mono2f(bv[0]); r.y = mono2f(bv[1]);
            r.z = mono2f(bv[2]); r.w = mono2f(bv[3]);
            reinterpret_cast<float4*>(x_out)[row] = r;
        }
    }
}

// ---------------------------------------------------------------------------
extern "C" void kernel_launch(void* const* d_in, const int* in_sizes, int n_in,
                              void* d_out, int out_size) {
    const float* x = (const float*)d_in[0];   // 32*2048*1024
    const float* y = (const float*)d_in[1];   // 8*32*2048*64
    const float* z = (const float*)d_in[2];   // 32*4096*512

    float* out   = (float*)d_out;
    float* x_out = out;
    float* y_out = out + 262144;
    float* z_val = out + 278528;
    float* z_idx = out + 671744;

    mega<<<24832, 256>>>(x, y, z, x_out, y_out, z_val, z_idx);
}